// round 1
// baseline (speedup 1.0000x reference)
#include <cuda_runtime.h>
#include <cuda_bf16.h>
#include <math.h>

// Problem constants (from reference): B=2, L=2048, H=16, Dh=64, D=1024
#define BB 2
#define LL 2048
#define NH 16
#define DH 64
#define DM 1024
#define MROWS (BB * LL)          // 4096
#define PAD_START 1792           // keys >= this are masked (static in reference)
#define ATTN_SCALE 0.125f        // 1/sqrt(64)

// Scratch (allocation-free rule: __device__ globals)
__device__ float g_Q[MROWS * DM];
__device__ float g_K[MROWS * DM];
__device__ float g_V[MROWS * DM];
__device__ float g_C[MROWS * DM];

// ---------------------------------------------------------------------------
// GEMM: Y[M,N] = X[M,K] @ W[N,K]^T + b[N]   (torch Linear convention)
// 64x64 tile, BK=16, 256 threads, 4x4 microtile per thread.
// ---------------------------------------------------------------------------
#define TM 64
#define TN 64
#define TK 16

__global__ __launch_bounds__(256) void gemm_bias_kernel(
    const float* __restrict__ X, const float* __restrict__ W,
    const float* __restrict__ bias, float* __restrict__ Y,
    int M, int N, int K)
{
    __shared__ float Xs[TM][TK + 1];
    __shared__ float Ws[TN][TK + 1];

    const int tx = threadIdx.x;   // 0..15
    const int ty = threadIdx.y;   // 0..15
    const int tid = ty * 16 + tx;
    const int row0 = blockIdx.y * TM;
    const int col0 = blockIdx.x * TN;

    float acc[4][4];
#pragma unroll
    for (int i = 0; i < 4; i++)
#pragma unroll
        for (int j = 0; j < 4; j++) acc[i][j] = 0.f;

    for (int k0 = 0; k0 < K; k0 += TK) {
#pragma unroll
        for (int i = 0; i < 4; i++) {
            int idx = tid + i * 256;          // 0..1023
            int r = idx / TK, c = idx % TK;
            Xs[r][c] = X[(size_t)(row0 + r) * K + k0 + c];
            Ws[r][c] = W[(size_t)(col0 + r) * K + k0 + c];
        }
        __syncthreads();
#pragma unroll
        for (int kk = 0; kk < TK; kk++) {
            float xv[4], wv[4];
#pragma unroll
            for (int i = 0; i < 4; i++) xv[i] = Xs[ty * 4 + i][kk];
#pragma unroll
            for (int j = 0; j < 4; j++) wv[j] = Ws[tx * 4 + j][kk];
#pragma unroll
            for (int i = 0; i < 4; i++)
#pragma unroll
                for (int j = 0; j < 4; j++) acc[i][j] += xv[i] * wv[j];
        }
        __syncthreads();
    }

#pragma unroll
    for (int i = 0; i < 4; i++) {
        int r = row0 + ty * 4 + i;
#pragma unroll
        for (int j = 0; j < 4; j++) {
            int c = col0 + tx * 4 + j;
            Y[(size_t)r * N + c] = acc[i][j] + bias[c];
        }
    }
}

// ---------------------------------------------------------------------------
// Flash-attention (fp32, online softmax).
// grid = (L/BR, NH, BB), block = BR = 128 threads; one q-row per thread.
// K/V tiles (64x64) staged in smem, read as broadcast float4.
// Scores staged in padded smem (stride 65) to keep registers at q[64]+acc[64].
// ---------------------------------------------------------------------------
#define BR 128
#define BC 64
// dynamic smem floats: Ks 64*64, Vs 64*64, Ss BR*65
#define ATTN_SMEM_FLOATS (2 * BC * DH + BR * 65)
#define ATTN_SMEM_BYTES (ATTN_SMEM_FLOATS * 4)

__global__ __launch_bounds__(BR) void attn_kernel(
    const float* __restrict__ Q, const float* __restrict__ K,
    const float* __restrict__ V, float* __restrict__ O)
{
    extern __shared__ float smem[];
    float* Ks = smem;                    // [BC][DH]
    float* Vs = smem + BC * DH;          // [BC][DH]
    float* Ss = smem + 2 * BC * DH;      // [BR][65]

    const int t = threadIdx.x;
    const int h = blockIdx.y;
    const int b = blockIdx.z;
    const int q0 = blockIdx.x * BR;
    const int l = q0 + t;                // query index within batch

    const float* qptr = Q + (size_t)(b * LL + l) * DM + h * DH;
    float q[DH];
#pragma unroll
    for (int c4 = 0; c4 < DH / 4; c4++) {
        float4 v = *(const float4*)(qptr + c4 * 4);
        q[c4 * 4 + 0] = v.x; q[c4 * 4 + 1] = v.y;
        q[c4 * 4 + 2] = v.z; q[c4 * 4 + 3] = v.w;
    }

    float acc[DH];
#pragma unroll
    for (int c = 0; c < DH; c++) acc[c] = 0.f;
    float m = -1e30f, lsum = 0.f;

    const int kv_limit_thread = min(l + 1, PAD_START);
    const int kv_limit_block  = min(q0 + BR, PAD_START);

    for (int k0 = 0; k0 < kv_limit_block; k0 += BC) {
        // stage K/V tile: BC*DH floats = 1024 float4, 128 threads -> 8 iters
        const int rowbase = b * LL + k0;
        for (int i = t; i < BC * DH / 4; i += BR) {
            int r = i >> 4;            // 16 float4 per row
            int c4 = i & 15;
            ((float4*)Ks)[i] = *(const float4*)(K + (size_t)(rowbase + r) * DM + h * DH + c4 * 4);
            ((float4*)Vs)[i] = *(const float4*)(V + (size_t)(rowbase + r) * DM + h * DH + c4 * 4);
        }
        __syncthreads();

        const int jmax = kv_limit_thread - k0;  // may be <=0 (fully masked tile)
        float tmax = -1e30f;
#pragma unroll 4
        for (int j = 0; j < BC; j++) {
            float s = 0.f;
            const float4* kr = (const float4*)(Ks + j * DH);
#pragma unroll
            for (int c4 = 0; c4 < DH / 4; c4++) {
                float4 kv = kr[c4];
                s += q[c4 * 4 + 0] * kv.x;
                s += q[c4 * 4 + 1] * kv.y;
                s += q[c4 * 4 + 2] * kv.z;
                s += q[c4 * 4 + 3] * kv.w;
            }
            s = (j < jmax) ? s * ATTN_SCALE : -1e30f;
            tmax = fmaxf(tmax, s);
            Ss[t * 65 + j] = s;
        }

        float mnew = fmaxf(m, tmax);
        float corr = __expf(m - mnew);
        lsum *= corr;
#pragma unroll
        for (int c = 0; c < DH; c++) acc[c] *= corr;
        m = mnew;

#pragma unroll 2
        for (int j = 0; j < BC; j++) {
            float p = __expf(Ss[t * 65 + j] - mnew);
            lsum += p;
            const float4* vr = (const float4*)(Vs + j * DH);
#pragma unroll
            for (int c4 = 0; c4 < DH / 4; c4++) {
                float4 vv = vr[c4];
                acc[c4 * 4 + 0] += p * vv.x;
                acc[c4 * 4 + 1] += p * vv.y;
                acc[c4 * 4 + 2] += p * vv.z;
                acc[c4 * 4 + 3] += p * vv.w;
            }
        }
        __syncthreads();
    }

    const float inv = 1.f / lsum;
    float* optr = O + (size_t)(b * LL + l) * DM + h * DH;
#pragma unroll
    for (int c4 = 0; c4 < DH / 4; c4++) {
        float4 o4;
        o4.x = acc[c4 * 4 + 0] * inv;
        o4.y = acc[c4 * 4 + 1] * inv;
        o4.z = acc[c4 * 4 + 2] * inv;
        o4.w = acc[c4 * 4 + 3] * inv;
        *(float4*)(optr + c4 * 4) = o4;
    }
}

// ---------------------------------------------------------------------------
extern "C" void kernel_launch(void* const* d_in, const int* in_sizes, int n_in,
                              void* d_out, int out_size)
{
    const float* X  = (const float*)d_in[0];
    const float* Wq = (const float*)d_in[1];
    const float* bq = (const float*)d_in[2];
    const float* Wk = (const float*)d_in[3];
    const float* bk = (const float*)d_in[4];
    const float* Wv = (const float*)d_in[5];
    const float* bv = (const float*)d_in[6];
    const float* Wo = (const float*)d_in[7];
    const float* bo = (const float*)d_in[8];
    float* out = (float*)d_out;

    float *Qp, *Kp, *Vp, *Cp;
    cudaGetSymbolAddress((void**)&Qp, g_Q);
    cudaGetSymbolAddress((void**)&Kp, g_K);
    cudaGetSymbolAddress((void**)&Vp, g_V);
    cudaGetSymbolAddress((void**)&Cp, g_C);

    cudaFuncSetAttribute(attn_kernel,
                         cudaFuncAttributeMaxDynamicSharedMemorySize,
                         ATTN_SMEM_BYTES);

    dim3 ggrid(DM / TN, MROWS / TM);   // (16, 64)
    dim3 gblk(16, 16);

    gemm_bias_kernel<<<ggrid, gblk>>>(X, Wq, bq, Qp, MROWS, DM, DM);
    gemm_bias_kernel<<<ggrid, gblk>>>(X, Wk, bk, Kp, MROWS, DM, DM);
    gemm_bias_kernel<<<ggrid, gblk>>>(X, Wv, bv, Vp, MROWS, DM, DM);

    dim3 agrid(LL / BR, NH, BB);       // (16, 16, 2)
    attn_kernel<<<agrid, BR, ATTN_SMEM_BYTES>>>(Qp, Kp, Vp, Cp);

    gemm_bias_kernel<<<ggrid, gblk>>>(Cp, Wo, bo, out, MROWS, DM, DM);
}